// round 12
// baseline (speedup 1.0000x reference)
#include <cuda_runtime.h>
#include <cuda_fp16.h>
#include <cstdint>

// ---------------------------------------------------------------- constants
#define B_   8
#define CG   192
#define OG   192
#define HP   66
#define WP   322
#define HC   64
#define WC   320
#define KTOT 1344            // CG * 7 hex taps
#define NCH  21              // KTOT / 64  (Kc = 64)
#define NTHR 256

#define NTILE_MAIN 2432      // 304 CTAs x 8 tiles, perfectly balanced
#define NTAIL_CTAS 256       // remaining 128 tiles as 256 half-tiles (32 px)

// Weights (half) in mma-fragment layout:
// [chunk32x42][ks2][nb24][lane32][4 halves] (reg*2+half)
__device__ __half g_Kt[42 * 6144];
__device__ unsigned g_tile;

// tap -> offset (dy*WP + dx) for hex positions
__constant__ int c_off[7] = {WP + 1, 0, 1, WP + 2, 2 * WP + 2, 2 * WP + 1, WP};

// ---------------------------------------------------------------- utils
__device__ __forceinline__ uint32_t smem_u32(const void* p) {
    uint32_t a;
    asm("{ .reg .u64 t; cvta.to.shared.u64 t, %1; cvt.u32.u64 %0, t; }"
        : "=r"(a) : "l"(p));
    return a;
}

// ---------------------------------------------------------------- prep
// One thread per (og, cg, tap); also resets the tile counter.
__global__ void prep_kernel(const float* __restrict__ w) {
    if (blockIdx.x == 0 && threadIdx.x == 0) g_tile = 0;
    int idx = blockIdx.x * blockDim.x + threadIdx.x;
    if (idx >= OG * CG * 7) return;
    int t   = idx % 7;
    int rem = idx / 7;
    int cg  = rem % CG;
    int og  = rem / CG;
    int o = og / 12, g = og % 12;
    int c = cg / 12, h = cg % 12;
    int fg = g / 6, rg = g % 6;
    int fh = h / 6, rh = h % 6;
    int f = fg ^ fh;
    int r = (fg == 0) ? ((rh - rg + 6) % 6) : ((rg - rh + 6) % 6);
    int p = f * 6 + r;

    int tap;
    if (t == 0) tap = 0;
    else {
        int i = t - 1;
        int src = (fg == 0) ? ((i - rg + 12) % 6) : ((rg - i + 12) % 6);
        tap = 1 + src;
    }
    float val = w[(((o * 16 + c) * 12 + p) * 7) + tap];

    int nb = og >> 3;
    int n  = og & 7;
    int k    = cg * 7 + t;
    int ch   = k >> 5;
    int kk   = k & 31;
    int ks   = kk >> 4;
    int kk16 = kk & 15;
    int lane = n * 4 + ((kk16 & 7) >> 1);
    int reg  = kk16 >> 3;
    int half = kk16 & 1;
    g_Kt[(size_t)(((ch * 2 + ks) * 24 + nb) * 32 + lane) * 4 + reg * 2 + half] =
        __float2half_rn(val);
}

// ---------------------------------------------------------------- shared
// SMEM: A 2 x 8KB at 0 ; B 2 x 24KB at 16384 ; bias at 65536 ; tile at 66304
#define SMEM_B_OFF 16384
#define SMEM_BIAS  65536
#define SMEM_TILE  66304
#define SMEM_TOT   (66304 + 16)

#define LOAD_A_CHUNK(ch, EN)                                                  \
    do {                                                                      \
        _Pragma("unroll")                                                     \
        for (int u = 0; u < 2; u++) {                                         \
            int k0 = (ch) * 64 + u * 32 + kpl * 2;                            \
            int k1 = k0 + 1;                                                  \
            const float* p0 = xb + (size_t)(k0 / 7) * plane + c_off[k0 % 7];  \
            const float* p1 = xb + (size_t)(k1 / 7) * plane + c_off[k1 % 7];  \
            _Pragma("unroll")                                                 \
            for (int e = 0; e < (EN); e++) {                                  \
                float f0 = __ldg(p0 + e * 16);                                \
                float f1 = __ldg(p1 + e * 16);                                \
                __half2 hh = __halves2half2(__float2half_rn(f0),              \
                                            __float2half_rn(f1));             \
                v[u][e] = *(uint32_t*)&hh;                                    \
            }                                                                 \
        }                                                                     \
    } while (0)

#define STORE_A_CHUNK(stage, EN)                                              \
    do {                                                                      \
        uint32_t base = a_sts0 + (stage) * 8192;                              \
        _Pragma("unroll")                                                     \
        for (int u = 0; u < 2; u++)                                           \
            _Pragma("unroll")                                                 \
            for (int e = 0; e < (EN); e++)                                    \
                asm volatile("st.shared.b32 [%0], %1;"                        \
                             :: "r"(base + u * 4096 + e * 512), "r"(v[u][e]));\
    } while (0)

#define LOAD_B_CHUNK(ch, stage)                                               \
    do {                                                                      \
        const __half* src = g_Kt + (size_t)(ch) * 12288 + tid * 8;            \
        uint32_t dst = sb + SMEM_B_OFF + (stage) * 24576 + tid * 16;          \
        _Pragma("unroll")                                                     \
        for (int i = 0; i < 6; i++)                                           \
            asm volatile("cp.async.cg.shared.global [%0], [%1], 16;"          \
                         :: "r"(dst + i * 4096), "l"(src + i * 2048) : "memory"); \
        asm volatile("cp.async.commit_group;" ::: "memory");                  \
    } while (0)

// ---------------------------------------------------------------- main conv
// Persistent CTAs, dynamic queue over 2432 tiles (8 per CTA, no tail).
// Tile = 64 px (1 row x 64 cols) x 192 og. 8 warps: 2M x 4N, warp tile 32x48.
__global__ void __launch_bounds__(NTHR, 2) conv_mma(
    const float* __restrict__ x,
    const float* __restrict__ bias,
    float* __restrict__ out)
{
    extern __shared__ char smem[];
    const uint32_t sb = smem_u32(smem);
    const int tid  = threadIdx.x;
    const int lane = tid & 31;
    const int wrp  = tid >> 5;
    const int wm   = wrp >> 2;      // 0..1
    const int wn   = wrp & 3;       // 0..3

    if (tid < OG) ((float*)(smem + SMEM_BIAS))[tid] = bias[tid / 12];

    const int kpl  = (lane >> 4) + wrp * 2;     // 0..15 within a 32-K sub
    const int p_ks = kpl >> 3;
    const int l_c  = (kpl & 3) + (lane & 7) * 4;
    const int sreg = ((lane >> 3) & 1) + ((kpl >> 2) & 1) * 2;
    const uint32_t a_sts0 = sb + (uint32_t)(p_ks * 2048 + l_c * 16 + sreg * 4);
    const int mcol = lane & 15;

    const size_t plane = (size_t)HP * WP;
    volatile unsigned* s_tile = (volatile unsigned*)(smem + SMEM_TILE);

    uint32_t v[2][4];
    float acc[2][6][4];

    while (true) {
        if (tid == 0) *s_tile = atomicAdd(&g_tile, 1u);
        __syncthreads();
        unsigned t = *s_tile;
        if (t >= NTILE_MAIN) break;

        const int bx  = t % 5;
        const int rem = t / 5;
        const int cy  = rem & 63;
        const int b   = rem >> 6;
        const int cx0 = bx * 64;

        const float* xb = x + (size_t)b * CG * plane + (size_t)cy * WP
                        + cx0 + mcol;

#pragma unroll
        for (int i = 0; i < 2; i++)
#pragma unroll
            for (int j = 0; j < 6; j++)
#pragma unroll
                for (int q = 0; q < 4; q++) acc[i][j][q] = 0.f;

        LOAD_A_CHUNK(0, 4);
        LOAD_B_CHUNK(0, 0);
        STORE_A_CHUNK(0, 4);
        asm volatile("cp.async.wait_group 0;" ::: "memory");
        __syncthreads();

        for (int ch = 0; ch < NCH; ch++) {
            const int s = ch & 1;
            if (ch + 1 < NCH) {
                LOAD_A_CHUNK(ch + 1, 4);
                LOAD_B_CHUNK(ch + 1, s ^ 1);
            }

            const uint32_t Ab = sb + s * 8192 + (uint32_t)(wm * 2 * 512 + lane * 16);
            const uint32_t Bb = sb + SMEM_B_OFF + s * 24576
                              + (uint32_t)((wn * 6) * 256 + lane * 8);
#pragma unroll
            for (int ks = 0; ks < 4; ks++) {
                uint32_t a[2][4];
#pragma unroll
                for (int mf = 0; mf < 2; mf++)
                    asm volatile("ld.shared.v4.b32 {%0,%1,%2,%3}, [%4];"
                        : "=r"(a[mf][0]), "=r"(a[mf][1]), "=r"(a[mf][2]), "=r"(a[mf][3])
                        : "r"(Ab + ks * 2048 + mf * 512));
                uint32_t bf[6][2];
#pragma unroll
                for (int nf = 0; nf < 6; nf++)
                    asm volatile("ld.shared.v2.b32 {%0,%1}, [%2];"
                        : "=r"(bf[nf][0]), "=r"(bf[nf][1])
                        : "r"(Bb + ks * 6144 + nf * 256));
#pragma unroll
                for (int mf = 0; mf < 2; mf++)
#pragma unroll
                    for (int nf = 0; nf < 6; nf++)
                        asm volatile(
                            "mma.sync.aligned.m16n8k16.row.col.f32.f16.f16.f32 "
                            "{%0,%1,%2,%3}, {%4,%5,%6,%7}, {%8,%9}, {%0,%1,%2,%3};"
                            : "+f"(acc[mf][nf][0]), "+f"(acc[mf][nf][1]),
                              "+f"(acc[mf][nf][2]), "+f"(acc[mf][nf][3])
                            : "r"(a[mf][0]), "r"(a[mf][1]), "r"(a[mf][2]), "r"(a[mf][3]),
                              "r"(bf[nf][0]), "r"(bf[nf][1]));
            }

            if (ch + 1 < NCH) STORE_A_CHUNK(s ^ 1, 4);
            asm volatile("cp.async.wait_group 0;" ::: "memory");
            __syncthreads();
        }

        // epilogue: bias + interior row cy+1, fused row boundaries
        const float* bs = (const float*)(smem + SMEM_BIAS);
#pragma unroll
        for (int mf = 0; mf < 2; mf++) {
#pragma unroll
            for (int half = 0; half < 2; half++) {
                int m = wm * 32 + mf * 16 + (lane >> 2) + half * 8;   // 0..63
                float* obase = out + (size_t)b * OG * plane + (cx0 + m + 1);
                float* orow  = obase + (size_t)(cy + 1) * WP;
#pragma unroll
                for (int nf = 0; nf < 6; nf++) {
                    int og = wn * 48 + nf * 8 + (lane & 3) * 2;
                    float d0 = acc[mf][nf][half * 2 + 0] + bs[og];
                    float d1 = acc[mf][nf][half * 2 + 1] + bs[og + 1];
                    orow[(size_t)og * plane]       = d0;
                    orow[(size_t)(og + 1) * plane] = d1;
                    if (cy == 63) {
                        obase[(size_t)og * plane]       = d0;
                        obase[(size_t)(og + 1) * plane] = d1;
                    }
                    if (cy == 0) {
                        obase[(size_t)og * plane + 65 * WP]       = d0;
                        obase[(size_t)(og + 1) * plane + 65 * WP] = d1;
                    }
                }
            }
        }
    }
}

// ---------------------------------------------------------------- tail conv
// The last 128 tiles as 256 half-tiles (32 px x 192 og, full K). One tile
// per CTA, no queue. Same layouts; mf=1 path (verified in R9).
__global__ void __launch_bounds__(NTHR, 2) conv_tail(
    const float* __restrict__ x,
    const float* __restrict__ bias,
    float* __restrict__ out)
{
    extern __shared__ char smem[];
    const uint32_t sb = smem_u32(smem);
    const int tid  = threadIdx.x;
    const int lane = tid & 31;
    const int wrp  = tid >> 5;
    const int wm   = wrp >> 2;      // 0..1
    const int wn   = wrp & 3;       // 0..3

    if (tid < OG) ((float*)(smem + SMEM_BIAS))[tid] = bias[tid / 12];

    const int kpl  = (lane >> 4) + wrp * 2;
    const int p_ks = kpl >> 3;
    const int l_c  = (kpl & 3) + (lane & 7) * 4;
    const int sreg = ((lane >> 3) & 1) + ((kpl >> 2) & 1) * 2;
    const uint32_t a_sts0 = sb + (uint32_t)(p_ks * 2048 + l_c * 16 + sreg * 4);
    const int mcol = lane & 15;

    const size_t plane = (size_t)HP * WP;

    const unsigned u = blockIdx.x;
    const int torig = NTILE_MAIN + (int)(u >> 1);
    const int h     = u & 1;
    const int bx  = torig % 5;
    const int rem = torig / 5;
    const int cy  = rem & 63;
    const int b   = rem >> 6;
    const int cx0 = bx * 64 + h * 32;

    const float* xb = x + (size_t)b * CG * plane + (size_t)cy * WP + cx0 + mcol;

    uint32_t v[2][4];
    float acc[1][6][4];
#pragma unroll
    for (int j = 0; j < 6; j++)
#pragma unroll
        for (int q = 0; q < 4; q++) acc[0][j][q] = 0.f;

    __syncthreads();   // bias visible

    LOAD_A_CHUNK(0, 2);
    LOAD_B_CHUNK(0, 0);
    STORE_A_CHUNK(0, 2);
    asm volatile("cp.async.wait_group 0;" ::: "memory");
    __syncthreads();

    for (int ch = 0; ch < NCH; ch++) {
        const int s = ch & 1;
        if (ch + 1 < NCH) {
            LOAD_A_CHUNK(ch + 1, 2);
            LOAD_B_CHUNK(ch + 1, s ^ 1);
        }

        const uint32_t Ab = sb + s * 8192 + (uint32_t)(wm * 512 + lane * 16);
        const uint32_t Bb = sb + SMEM_B_OFF + s * 24576
                          + (uint32_t)((wn * 6) * 256 + lane * 8);
#pragma unroll
        for (int ks = 0; ks < 4; ks++) {
            uint32_t a[1][4];
            asm volatile("ld.shared.v4.b32 {%0,%1,%2,%3}, [%4];"
                : "=r"(a[0][0]), "=r"(a[0][1]), "=r"(a[0][2]), "=r"(a[0][3])
                : "r"(Ab + ks * 2048));
            uint32_t bf[6][2];
#pragma unroll
            for (int nf = 0; nf < 6; nf++)
                asm volatile("ld.shared.v2.b32 {%0,%1}, [%2];"
                    : "=r"(bf[nf][0]), "=r"(bf[nf][1])
                    : "r"(Bb + ks * 6144 + nf * 256));
#pragma unroll
            for (int nf = 0; nf < 6; nf++)
                asm volatile(
                    "mma.sync.aligned.m16n8k16.row.col.f32.f16.f16.f32 "
                    "{%0,%1,%2,%3}, {%4,%5,%6,%7}, {%8,%9}, {%0,%1,%2,%3};"
                    : "+f"(acc[0][nf][0]), "+f"(acc[0][nf][1]),
                      "+f"(acc[0][nf][2]), "+f"(acc[0][nf][3])
                    : "r"(a[0][0]), "r"(a[0][1]), "r"(a[0][2]), "r"(a[0][3]),
                      "r"(bf[nf][0]), "r"(bf[nf][1]));
        }

        if (ch + 1 < NCH) STORE_A_CHUNK(s ^ 1, 2);
        asm volatile("cp.async.wait_group 0;" ::: "memory");
        __syncthreads();
    }

    // epilogue: bias + interior row cy+1, fused row boundaries
    const float* bs = (const float*)(smem + SMEM_BIAS);
#pragma unroll
    for (int half = 0; half < 2; half++) {
        int m = wm * 16 + (lane >> 2) + half * 8;   // 0..31
        float* obase = out + (size_t)b * OG * plane + (cx0 + m + 1);
        float* orow  = obase + (size_t)(cy + 1) * WP;
#pragma unroll
        for (int nf = 0; nf < 6; nf++) {
            int og = wn * 48 + nf * 8 + (lane & 3) * 2;
            float d0 = acc[0][nf][0 + half * 2] + bs[og];
            float d1 = acc[0][nf][1 + half * 2] + bs[og + 1];
            orow[(size_t)og * plane]       = d0;
            orow[(size_t)(og + 1) * plane] = d1;
            if (cy == 63) {
                obase[(size_t)og * plane]       = d0;
                obase[(size_t)(og + 1) * plane] = d1;
            }
            if (cy == 0) {
                obase[(size_t)og * plane + 65 * WP]       = d0;
                obase[(size_t)(og + 1) * plane + 65 * WP] = d1;
            }
        }
    }
}

// ---------------------------------------------------------------- boundary
// Columns x=0 and x=321 only (rows fused into conv epilogues).
__global__ void boundary_cols_kernel(float* __restrict__ out) {
    int idx = blockIdx.x * blockDim.x + threadIdx.x;
    int total = B_ * OG * HP * 2;    // 202752
    if (idx >= total) return;

    int side = idx & 1;
    int rem  = idx >> 1;
    int y    = rem % HP;
    int rem2 = rem / HP;
    int og   = rem2 % OG;
    int b    = rem2 / OG;

    int xx = side ? (WP - 1) : 0;
    int sx = side ? 1 : (WP - 2);
    int dt = side ? -1 : 1;
    int sy = y;
    if (y == 0)            sy = HP - 2;
    else if (y == HP - 1)  sy = 1;

    int o = og / 12, t = og % 12;
    int f = t / 6,   rr = t % 6;
    int gp = f * 6 + ((rr + dt + 6) % 6);
    int og_src = o * 12 + gp;

    out[((size_t)(b * OG + og) * HP + y) * WP + xx] =
        out[((size_t)(b * OG + og_src) * HP + sy) * WP + sx];
}

// ---------------------------------------------------------------- launch
extern "C" void kernel_launch(void* const* d_in, const int* in_sizes, int n_in,
                              void* d_out, int out_size) {
    (void)in_sizes; (void)n_in; (void)out_size;
    const float* x    = (const float*)d_in[0];
    const float* w    = (const float*)d_in[1];
    const float* bias = (const float*)d_in[2];
    float* out = (float*)d_out;

    cudaFuncSetAttribute(conv_mma, cudaFuncAttributeMaxDynamicSharedMemorySize,
                         SMEM_TOT);
    cudaFuncSetAttribute(conv_tail, cudaFuncAttributeMaxDynamicSharedMemorySize,
                         SMEM_TOT);

    prep_kernel<<<(OG * CG * 7 + 255) / 256, 256>>>(w);

    conv_mma<<<304, NTHR, SMEM_TOT>>>(x, bias, out);

    conv_tail<<<NTAIL_CTAS, NTHR, SMEM_TOT>>>(x, bias, out);

    int total = B_ * OG * HP * 2;
    boundary_cols_kernel<<<(total + 255) / 256, 256>>>(out);
}

// round 13
// speedup vs baseline: 1.1202x; 1.1202x over previous
#include <cuda_runtime.h>
#include <cuda_fp16.h>
#include <cstdint>

// ---------------------------------------------------------------- constants
#define B_   8
#define CG   192
#define OG   192
#define HP   66
#define WP   322
#define HC   64
#define WC   320
#define KTOT 1344            // CG * 7 hex taps
#define NCH  14              // KTOT / 96  (Kc = 96)
#define NTHR 256
#define NTILE 2560           // 5 x 64 x 8

// Weights (half) in mma-fragment layout:
// [chunk32x42][ks2][nb24][lane32][4 halves] (reg*2+half)
__device__ __half g_Kt[42 * 6144];
__device__ unsigned g_tile;

// tap -> offset (dy*WP + dx) for hex positions
__constant__ int c_off[7] = {WP + 1, 0, 1, WP + 2, 2 * WP + 2, 2 * WP + 1, WP};

// ---------------------------------------------------------------- utils
__device__ __forceinline__ uint32_t smem_u32(const void* p) {
    uint32_t a;
    asm("{ .reg .u64 t; cvta.to.shared.u64 t, %1; cvt.u32.u64 %0, t; }"
        : "=r"(a) : "l"(p));
    return a;
}

// ---------------------------------------------------------------- prep
// One thread per (og, cg, tap); also resets the tile counter.
__global__ void prep_kernel(const float* __restrict__ w) {
    if (blockIdx.x == 0 && threadIdx.x == 0) g_tile = 0;
    int idx = blockIdx.x * blockDim.x + threadIdx.x;
    if (idx >= OG * CG * 7) return;
    int t   = idx % 7;
    int rem = idx / 7;
    int cg  = rem % CG;
    int og  = rem / CG;
    int o = og / 12, g = og % 12;
    int c = cg / 12, h = cg % 12;
    int fg = g / 6, rg = g % 6;
    int fh = h / 6, rh = h % 6;
    int f = fg ^ fh;
    int r = (fg == 0) ? ((rh - rg + 6) % 6) : ((rg - rh + 6) % 6);
    int p = f * 6 + r;

    int tap;
    if (t == 0) tap = 0;
    else {
        int i = t - 1;
        int src = (fg == 0) ? ((i - rg + 12) % 6) : ((rg - i + 12) % 6);
        tap = 1 + src;
    }
    float val = w[(((o * 16 + c) * 12 + p) * 7) + tap];

    int nb = og >> 3;
    int n  = og & 7;
    int k    = cg * 7 + t;
    int ch   = k >> 5;
    int kk   = k & 31;
    int ks   = kk >> 4;
    int kk16 = kk & 15;
    int lane = n * 4 + ((kk16 & 7) >> 1);
    int reg  = kk16 >> 3;
    int half = kk16 & 1;
    g_Kt[(size_t)(((ch * 2 + ks) * 24 + nb) * 32 + lane) * 4 + reg * 2 + half] =
        __float2half_rn(val);
}

// ---------------------------------------------------------------- conv
// Persistent CTAs, dynamic tile queue. Tile = 64 px (1 row x 64 cols) x 192 og.
// 8 warps: 2M x 4N, warp tile 32x48. Kc = 96 (three 32-K subs), 14 iterations.
// SMEM: A 2 x 12KB at 0 ; B 2 x 36KB at 24576 ; bias at 98304 ; tile at 99072
#define SMEM_B_OFF 24576
#define SMEM_BIAS  98304
#define SMEM_TILE  99072
#define SMEM_TOT   (99072 + 16)

__global__ void __launch_bounds__(NTHR, 2) conv_mma(
    const float* __restrict__ x,
    const float* __restrict__ bias,
    float* __restrict__ out)
{
    extern __shared__ char smem[];
    const uint32_t sb = smem_u32(smem);
    const int tid  = threadIdx.x;
    const int lane = tid & 31;
    const int wrp  = tid >> 5;
    const int wm   = wrp >> 2;      // 0..1
    const int wn   = wrp & 3;       // 0..3

    if (tid < OG) ((float*)(smem + SMEM_BIAS))[tid] = bias[tid / 12];

    // ---- A producer constants (tile-independent) ----
    const int kpl  = (lane >> 4) + wrp * 2;     // 0..15 within a 32-K sub
    const int p_ks = kpl >> 3;
    const int l_c  = (kpl & 3) + (lane & 7) * 4;
    const int sreg = ((lane >> 3) & 1) + ((kpl >> 2) & 1) * 2;
    const uint32_t a_sts0 = sb + (uint32_t)(p_ks * 2048 + l_c * 16 + sreg * 4);
    const int mcol = lane & 15;

    const size_t plane = (size_t)HP * WP;
    volatile unsigned* s_tile = (volatile unsigned*)(smem + SMEM_TILE);

    uint32_t v[3][4];
    float acc[2][6][4];

#define LOAD_A_CHUNK(ch)                                                      \
    do {                                                                      \
        _Pragma("unroll")                                                     \
        for (int u = 0; u < 3; u++) {                                         \
            int k0 = (ch) * 96 + u * 32 + kpl * 2;                            \
            int k1 = k0 + 1;                                                  \
            const float* p0 = xb + (size_t)(k0 / 7) * plane + c_off[k0 % 7];  \
            const float* p1 = xb + (size_t)(k1 / 7) * plane + c_off[k1 % 7];  \
            _Pragma("unroll")                                                 \
            for (int e = 0; e < 4; e++) {                                     \
                float f0 = __ldg(p0 + e * 16);                                \
                float f1 = __ldg(p1 + e * 16);                                \
                __half2 hh = __halves2half2(__float2half_rn(f0),              \
                                            __float2half_rn(f1));             \
                v[u][e] = *(uint32_t*)&hh;                                    \
            }                                                                 \
        }                                                                     \
    } while (0)

#define STORE_A_CHUNK(stage)                                                  \
    do {                                                                      \
        uint32_t base = a_sts0 + (stage) * 12288;                             \
        _Pragma("unroll")                                                     \
        for (int u = 0; u < 3; u++)                                           \
            _Pragma("unroll")                                                 \
            for (int e = 0; e < 4; e++)                                       \
                asm volatile("st.shared.b32 [%0], %1;"                        \
                             :: "r"(base + u * 4096 + e * 512), "r"(v[u][e]));\
    } while (0)

#define LOAD_B_CHUNK(ch, stage)                                               \
    do {                                                                      \
        const __half* src = g_Kt + (size_t)(ch) * 18432 + tid * 8;            \
        uint32_t dst = sb + SMEM_B_OFF + (stage) * 36864 + tid * 16;          \
        _Pragma("unroll")                                                     \
        for (int i = 0; i < 9; i++)                                           \
            asm volatile("cp.async.cg.shared.global [%0], [%1], 16;"          \
                         :: "r"(dst + i * 4096), "l"(src + i * 2048) : "memory"); \
        asm volatile("cp.async.commit_group;" ::: "memory");                  \
    } while (0)

    // ================= persistent tile loop =================
    while (true) {
        if (tid == 0) *s_tile = atomicAdd(&g_tile, 1u);
        __syncthreads();
        unsigned t = *s_tile;
        if (t >= NTILE) break;

        const int bx  = t % 5;
        const int rem = t / 5;
        const int cy  = rem & 63;
        const int b   = rem >> 6;
        const int cx0 = bx * 64;

        const float* xb = x + (size_t)b * CG * plane + (size_t)cy * WP
                        + cx0 + mcol;

#pragma unroll
        for (int i = 0; i < 2; i++)
#pragma unroll
            for (int j = 0; j < 6; j++)
#pragma unroll
                for (int q = 0; q < 4; q++) acc[i][j][q] = 0.f;

        // ---- stage 0 fill ----
        LOAD_A_CHUNK(0);
        LOAD_B_CHUNK(0, 0);
        STORE_A_CHUNK(0);
        asm volatile("cp.async.wait_group 0;" ::: "memory");
        __syncthreads();

        // ---- main K loop (14 chunks of 96) ----
        for (int ch = 0; ch < NCH; ch++) {
            const int s = ch & 1;
            if (ch + 1 < NCH) {
                LOAD_A_CHUNK(ch + 1);
                LOAD_B_CHUNK(ch + 1, s ^ 1);
            }

            const uint32_t Ab = sb + s * 12288 + (uint32_t)(wm * 1024 + lane * 16);
            const uint32_t Bb = sb + SMEM_B_OFF + s * 36864
                              + (uint32_t)(wn * 1536 + lane * 8);
#pragma unroll
            for (int ks = 0; ks < 6; ks++) {
                uint32_t a[2][4];
#pragma unroll
                for (int mf = 0; mf < 2; mf++)
                    asm volatile("ld.shared.v4.b32 {%0,%1,%2,%3}, [%4];"
                        : "=r"(a[mf][0]), "=r"(a[mf][1]), "=r"(a[mf][2]), "=r"(a[mf][3])
                        : "r"(Ab + ks * 2048 + mf * 512));
                uint32_t bf[6][2];
#pragma unroll
                for (int nf = 0; nf < 6; nf++)
                    asm volatile("ld.shared.v2.b32 {%0,%1}, [%2];"
                        : "=r"(bf[nf][0]), "=r"(bf[nf][1])
                        : "r"(Bb + ks * 6144 + nf * 256));
#pragma unroll
                for (int mf = 0; mf < 2; mf++)
#pragma unroll
                    for (int nf = 0; nf < 6; nf++)
                        asm volatile(
                            "mma.sync.aligned.m16n8k16.row.col.f32.f16.f16.f32 "
                            "{%0,%1,%2,%3}, {%4,%5,%6,%7}, {%8,%9}, {%0,%1,%2,%3};"
                            : "+f"(acc[mf][nf][0]), "+f"(acc[mf][nf][1]),
                              "+f"(acc[mf][nf][2]), "+f"(acc[mf][nf][3])
                            : "r"(a[mf][0]), "r"(a[mf][1]), "r"(a[mf][2]), "r"(a[mf][3]),
                              "r"(bf[nf][0]), "r"(bf[nf][1]));
            }

            if (ch + 1 < NCH) STORE_A_CHUNK(s ^ 1);
            asm volatile("cp.async.wait_group 0;" ::: "memory");
            __syncthreads();
        }

        // ---- epilogue: bias + interior row cy+1; fused row boundaries
        //      (cy==63 -> row 0, cy==0 -> row 65); fused column boundaries
        //      (x=320 -> col 0 with og-twist r-1; x=1 -> col 321 with r+1). ----
        const float* bs = (const float*)(smem + SMEM_BIAS);
#pragma unroll
        for (int mf = 0; mf < 2; mf++) {
#pragma unroll
            for (int half = 0; half < 2; half++) {
                int m = wm * 32 + mf * 16 + (lane >> 2) + half * 8;   // 0..63
                float* obase = out + (size_t)b * OG * plane + (cx0 + m + 1);
                float* orow  = obase + (size_t)(cy + 1) * WP;
                const bool colR = (bx == 4) && (m == 63);   // x = 320
                const bool colL = (bx == 0) && (m == 0);    // x = 1
#pragma unroll
                for (int nf = 0; nf < 6; nf++) {
                    int og = wn * 48 + nf * 8 + (lane & 3) * 2;
                    float d0 = acc[mf][nf][half * 2 + 0] + bs[og];
                    float d1 = acc[mf][nf][half * 2 + 1] + bs[og + 1];
                    orow[(size_t)og * plane]       = d0;
                    orow[(size_t)(og + 1) * plane] = d1;
                    if (cy == 63) {
                        obase[(size_t)og * plane]       = d0;
                        obase[(size_t)(og + 1) * plane] = d1;
                    }
                    if (cy == 0) {
                        obase[(size_t)og * plane + 65 * WP]       = d0;
                        obase[(size_t)(og + 1) * plane + 65 * WP] = d1;
                    }
                    if (colR | colL) {
                        // og twist: dest r = src r + dtw
                        int dtw = colR ? 5 : 1;   // -1 mod 6 : +1
                        int xt  = colR ? 0 : (WP - 1);
                        int r0  = og % 6;
                        int r1  = (og + 1) % 6;
                        int og0 = og - r0 + ((r0 + dtw) % 6);
                        int og1 = (og + 1) - r1 + ((r1 + dtw) % 6);
                        float* c0 = out + ((size_t)(b * OG + og0)) * plane + xt;
                        float* c1 = out + ((size_t)(b * OG + og1)) * plane + xt;
                        c0[(size_t)(cy + 1) * WP] = d0;
                        c1[(size_t)(cy + 1) * WP] = d1;
                        if (cy == 63) { c0[0] = d0; c1[0] = d1; }
                        if (cy == 0)  { c0[65 * WP] = d0; c1[65 * WP] = d1; }
                    }
                }
            }
        }
    }
}

// ---------------------------------------------------------------- launch
extern "C" void kernel_launch(void* const* d_in, const int* in_sizes, int n_in,
                              void* d_out, int out_size) {
    (void)in_sizes; (void)n_in; (void)out_size;
    const float* x    = (const float*)d_in[0];
    const float* w    = (const float*)d_in[1];
    const float* bias = (const float*)d_in[2];
    float* out = (float*)d_out;

    cudaFuncSetAttribute(conv_mma, cudaFuncAttributeMaxDynamicSharedMemorySize,
                         SMEM_TOT);

    prep_kernel<<<(OG * CG * 7 + 255) / 256, 256>>>(w);

    conv_mma<<<304, NTHR, SMEM_TOT>>>(x, bias, out);
}